// round 2
// baseline (speedup 1.0000x reference)
#include <cuda_runtime.h>
#include <cuda_bf16.h>
#include <math.h>

// Problem constants
#define T_TOK 49152          // B*S*N = 2*24*1024
#define HID   512
#define NEXP  8
#define MOEI  1024
#define SHI   2048
#define NSLOT (2 * T_TOK)    // top-2 -> exactly 2 slots per token

// ---------------------------------------------------------------------------
// Scratch (static __device__ arrays; no allocation anywhere)
// ---------------------------------------------------------------------------
__device__ float g_bufA[100663296];             // 2T*1024 == T*2048  (g / h)
__device__ float g_bufB[100663296];             // 2T*1024 == T*2048  (u)
__device__ float g_y  [(size_t)NSLOT * HID];    // per-slot expert output
__device__ float g_ys [(size_t)T_TOK * HID];    // shared-expert output
__device__ int   g_topk_idx[NSLOT];
__device__ float g_topk_w [NSLOT];
__device__ float g_sig    [T_TOK];
__device__ int   g_counts [NEXP];
__device__ int   g_offsets[NEXP];
__device__ int   g_cursor [NEXP];
__device__ int   g_slot_token[NSLOT];           // slot -> token
__device__ int   g_slot_of   [NSLOT];           // (token,k) -> slot

// ---------------------------------------------------------------------------
// 0) zero counters
// ---------------------------------------------------------------------------
__global__ void init_kernel() {
    int i = threadIdx.x;
    if (i < NEXP) { g_counts[i] = 0; g_cursor[i] = 0; }
}

// ---------------------------------------------------------------------------
// 1) router: logits, softmax, top-2, sigmoid(x@sgate); count experts
//    one warp per token, 8 warps / block
// ---------------------------------------------------------------------------
__global__ void __launch_bounds__(256) router_kernel(
    const float* __restrict__ x, const float* __restrict__ gw,
    const float* __restrict__ sg, float* __restrict__ logits_out)
{
    __shared__ float s_gw[HID * NEXP];
    __shared__ float s_sg[HID];
    for (int i = threadIdx.x; i < HID * NEXP; i += 256) s_gw[i] = gw[i];
    for (int i = threadIdx.x; i < HID; i += 256) s_sg[i] = sg[i];
    __syncthreads();

    int warp = threadIdx.x >> 5, lane = threadIdx.x & 31;
    int t = blockIdx.x * 8 + warp;
    const float* xr = x + (size_t)t * HID;

    float acc[NEXP];
#pragma unroll
    for (int e = 0; e < NEXP; e++) acc[e] = 0.f;
    float accs = 0.f;

#pragma unroll 4
    for (int i = 0; i < 16; i++) {
        int h = i * 32 + lane;
        float xv = xr[h];
#pragma unroll
        for (int e = 0; e < NEXP; e++) acc[e] += xv * s_gw[h * NEXP + e];
        accs += xv * s_sg[h];
    }
#pragma unroll
    for (int off = 16; off; off >>= 1) {
#pragma unroll
        for (int e = 0; e < NEXP; e++)
            acc[e] += __shfl_xor_sync(0xffffffff, acc[e], off);
        accs += __shfl_xor_sync(0xffffffff, accs, off);
    }

    if (lane == 0) {
        if (logits_out) {
#pragma unroll
            for (int e = 0; e < NEXP; e++) logits_out[(size_t)t * NEXP + e] = acc[e];
        }
        float m = acc[0];
#pragma unroll
        for (int e = 1; e < NEXP; e++) m = fmaxf(m, acc[e]);
        float p[NEXP], sum = 0.f;
#pragma unroll
        for (int e = 0; e < NEXP; e++) { p[e] = expf(acc[e] - m); sum += p[e]; }
        float inv = 1.f / sum;
#pragma unroll
        for (int e = 0; e < NEXP; e++) p[e] *= inv;

        int i1 = 0;
#pragma unroll
        for (int e = 1; e < NEXP; e++) if (p[e] > p[i1]) i1 = e;
        int i2 = (i1 == 0) ? 1 : 0;
#pragma unroll
        for (int e = 0; e < NEXP; e++) if (e != i1 && e != i2 && p[e] > p[i2]) i2 = e;

        g_topk_idx[2 * t]     = i1; g_topk_w[2 * t]     = p[i1];
        g_topk_idx[2 * t + 1] = i2; g_topk_w[2 * t + 1] = p[i2];
        atomicAdd(&g_counts[i1], 1);
        atomicAdd(&g_counts[i2], 1);
        g_sig[t] = 1.f / (1.f + expf(-accs));
    }
}

// ---------------------------------------------------------------------------
// 2) exclusive prefix over 8 counts
// ---------------------------------------------------------------------------
__global__ void prefix_kernel() {
    if (threadIdx.x == 0) {
        int s = 0;
        for (int e = 0; e < NEXP; e++) { g_offsets[e] = s; g_cursor[e] = s; s += g_counts[e]; }
    }
}

// ---------------------------------------------------------------------------
// 3) scatter tokens into per-expert slot lists
// ---------------------------------------------------------------------------
__global__ void scatter_kernel() {
    int t = blockIdx.x * 256 + threadIdx.x;
    if (t >= T_TOK) return;
#pragma unroll
    for (int k = 0; k < 2; k++) {
        int e = g_topk_idx[2 * t + k];
        int pos = atomicAdd(&g_cursor[e], 1);
        g_slot_token[pos] = t;
        g_slot_of[2 * t + k] = pos;
    }
}

// ---------------------------------------------------------------------------
// 4) fp32 SGEMM, 128x128x16 tile, 256 threads, 8x8 per thread.
//    C[base+r, :] = A_rows @ B_e ;  A rows either gathered tokens or slot rows.
// ---------------------------------------------------------------------------
__global__ void __launch_bounds__(256) sgemm_kernel(
    const float* __restrict__ A, const float* __restrict__ B, float* __restrict__ C,
    int N, int K, long strideB, int Mfixed, int useCounts, int useGather)
{
    __shared__ float As[16][132];   // transposed, padded
    __shared__ float Bs[16][128];

    int e = blockIdx.z;
    int M, base;
    if (useCounts) { M = g_counts[e]; base = g_offsets[e]; }
    else           { M = Mfixed;      base = 0; }
    int row0 = blockIdx.y * 128;
    if (row0 >= M) return;
    int col0 = blockIdx.x * 128;
    const float* Bp = B + (size_t)e * strideB;

    int tid = threadIdx.x;
    int ty8 = (tid >> 4) * 8;
    int tx8 = (tid & 15) * 8;

    // A-load lanes: v = tid + j*256 ; row = v>>2, k-quad = v&3
    const float* aptr[2];
#pragma unroll
    for (int j = 0; j < 2; j++) {
        int v = tid + j * 256;
        int r = v >> 2;
        int gr = row0 + r; if (gr > M - 1) gr = M - 1;
        long arow = useGather ? (long)g_slot_token[base + gr] : (long)(base + gr);
        aptr[j] = A + (size_t)arow * K + (v & 3) * 4;
    }
    // B-load lanes: v = tid + j*256 ; row = v>>5, col-quad = v&31
    const float* bptr[2];
#pragma unroll
    for (int j = 0; j < 2; j++) {
        int v = tid + j * 256;
        bptr[j] = Bp + (size_t)(v >> 5) * N + col0 + (v & 31) * 4;
    }

    float acc[8][8];
#pragma unroll
    for (int i = 0; i < 8; i++)
#pragma unroll
        for (int j = 0; j < 8; j++) acc[i][j] = 0.f;

    int nk = K >> 4;
    for (int kt = 0; kt < nk; kt++) {
#pragma unroll
        for (int j = 0; j < 2; j++) {
            int v = tid + j * 256;
            int r = v >> 2, ks = (v & 3) * 4;
            float4 av = *(const float4*)aptr[j];
            aptr[j] += 16;
            As[ks + 0][r] = av.x; As[ks + 1][r] = av.y;
            As[ks + 2][r] = av.z; As[ks + 3][r] = av.w;
        }
#pragma unroll
        for (int j = 0; j < 2; j++) {
            int v = tid + j * 256;
            *(float4*)&Bs[v >> 5][(v & 31) * 4] = *(const float4*)bptr[j];
            bptr[j] += (size_t)16 * N;
        }
        __syncthreads();
#pragma unroll
        for (int k = 0; k < 16; k++) {
            float4 a0 = *(const float4*)&As[k][ty8];
            float4 a1 = *(const float4*)&As[k][ty8 + 4];
            float4 b0 = *(const float4*)&Bs[k][tx8];
            float4 b1 = *(const float4*)&Bs[k][tx8 + 4];
            float a[8] = {a0.x, a0.y, a0.z, a0.w, a1.x, a1.y, a1.z, a1.w};
            float b[8] = {b0.x, b0.y, b0.z, b0.w, b1.x, b1.y, b1.z, b1.w};
#pragma unroll
            for (int i = 0; i < 8; i++)
#pragma unroll
                for (int j = 0; j < 8; j++) acc[i][j] += a[i] * b[j];
        }
        __syncthreads();
    }

#pragma unroll
    for (int i = 0; i < 8; i++) {
        int gr = row0 + ty8 + i;
        if (gr < M) {
            float* Cr = C + (size_t)(base + gr) * N + col0 + tx8;
            *(float4*)Cr       = make_float4(acc[i][0], acc[i][1], acc[i][2], acc[i][3]);
            *(float4*)(Cr + 4) = make_float4(acc[i][4], acc[i][5], acc[i][6], acc[i][7]);
        }
    }
}

// ---------------------------------------------------------------------------
// 5) SwiGLU activation: a = silu(a) * b  (in place into a), float4 per thread
// ---------------------------------------------------------------------------
__global__ void __launch_bounds__(256) act_kernel(float* __restrict__ a,
                                                  const float* __restrict__ b, int n4)
{
    int i = blockIdx.x * 256 + threadIdx.x;
    if (i >= n4) return;
    float4 g = ((const float4*)a)[i];
    float4 u = ((const float4*)b)[i];
    float4 r;
    r.x = g.x * (1.f / (1.f + __expf(-g.x))) * u.x;
    r.y = g.y * (1.f / (1.f + __expf(-g.y))) * u.y;
    r.z = g.z * (1.f / (1.f + __expf(-g.z))) * u.z;
    r.w = g.w * (1.f / (1.f + __expf(-g.w))) * u.w;
    ((float4*)a)[i] = r;
}

// ---------------------------------------------------------------------------
// 6) combine: out[t] = w0*y[s0] + w1*y[s1] + sig[t]*ys[t]
// ---------------------------------------------------------------------------
__global__ void __launch_bounds__(128) combine_kernel(float* __restrict__ out)
{
    int t = blockIdx.x;
    int j = threadIdx.x;                       // 128 float4 per row of 512
    float w0 = g_topk_w[2 * t], w1 = g_topk_w[2 * t + 1];
    int   s0 = g_slot_of[2 * t], s1 = g_slot_of[2 * t + 1];
    float sg = g_sig[t];
    const float4* y4  = (const float4*)g_y;
    const float4* ys4 = (const float4*)g_ys;
    float4 a = y4[(size_t)s0 * 128 + j];
    float4 b = y4[(size_t)s1 * 128 + j];
    float4 c = ys4[(size_t)t * 128 + j];
    float4 r;
    r.x = w0 * a.x + w1 * b.x + sg * c.x;
    r.y = w0 * a.y + w1 * b.y + sg * c.y;
    r.z = w0 * a.z + w1 * b.z + sg * c.z;
    r.w = w0 * a.w + w1 * b.w + sg * c.w;
    ((float4*)out)[(size_t)t * 128 + j] = r;
}

// ---------------------------------------------------------------------------
// launch
// ---------------------------------------------------------------------------
extern "C" void kernel_launch(void* const* d_in, const int* in_sizes, int n_in,
                              void* d_out, int out_size)
{
    const float* x     = (const float*)d_in[0];
    const float* gate  = (const float*)d_in[1];
    const float* w1    = (const float*)d_in[2];
    const float* w2    = (const float*)d_in[3];
    const float* w3    = (const float*)d_in[4];
    const float* sw1   = (const float*)d_in[5];
    const float* sw2   = (const float*)d_in[6];
    const float* sw3   = (const float*)d_in[7];
    const float* sgate = (const float*)d_in[8];
    float* out = (float*)d_out;

    float* logits = nullptr;
    if ((size_t)out_size >= (size_t)T_TOK * HID + (size_t)T_TOK * NEXP)
        logits = out + (size_t)T_TOK * HID;

    float* bufA = nullptr; float* bufB = nullptr; float* ybuf = nullptr; float* ysbuf = nullptr;
    cudaGetSymbolAddress((void**)&bufA,  g_bufA);
    cudaGetSymbolAddress((void**)&bufB,  g_bufB);
    cudaGetSymbolAddress((void**)&ybuf,  g_y);
    cudaGetSymbolAddress((void**)&ysbuf, g_ys);

    init_kernel<<<1, 32>>>();
    router_kernel<<<T_TOK / 8, 256>>>(x, gate, sgate, logits);
    prefix_kernel<<<1, 32>>>();
    scatter_kernel<<<T_TOK / 256, 256>>>();

    // MoE stage A: g = X_g @ w1[e], u = X_g @ w3[e]   (gathered rows)
    sgemm_kernel<<<dim3(MOEI / 128, T_TOK / 128, NEXP), 256>>>(
        x, w1, bufA, MOEI, HID, (long)HID * MOEI, 0, 1, 1);
    sgemm_kernel<<<dim3(MOEI / 128, T_TOK / 128, NEXP), 256>>>(
        x, w3, bufB, MOEI, HID, (long)HID * MOEI, 0, 1, 1);
    act_kernel<<<100663296 / (256 * 4), 256>>>(bufA, bufB, 100663296 / 4);
    // MoE stage B: y_slot = h @ w2[e]   (slot rows, no gather)
    sgemm_kernel<<<dim3(HID / 128, T_TOK / 128, NEXP), 256>>>(
        bufA, w2, ybuf, HID, MOEI, (long)MOEI * HID, 0, 1, 0);

    // Shared expert (dense over all T tokens)
    sgemm_kernel<<<dim3(SHI / 128, T_TOK / 128, 1), 256>>>(
        x, sw1, bufA, SHI, HID, 0L, T_TOK, 0, 0);
    sgemm_kernel<<<dim3(SHI / 128, T_TOK / 128, 1), 256>>>(
        x, sw3, bufB, SHI, HID, 0L, T_TOK, 0, 0);
    act_kernel<<<100663296 / (256 * 4), 256>>>(bufA, bufB, 100663296 / 4);
    sgemm_kernel<<<dim3(HID / 128, T_TOK / 128, 1), 256>>>(
        bufA, sw2, ysbuf, HID, SHI, 0L, T_TOK, 0, 0);

    combine_kernel<<<T_TOK, 128>>>(out);
}

// round 3
// speedup vs baseline: 2.4629x; 2.4629x over previous
#include <cuda_runtime.h>
#include <cuda_bf16.h>
#include <math.h>
#include <stdint.h>

// Problem constants
#define T_TOK 49152          // B*S*N = 2*24*1024
#define HID   512
#define NEXP  8
#define MOEI  1024
#define SHI   2048
#define NSLOT (2 * T_TOK)    // top-2 -> exactly 2 slots per token

// ---------------------------------------------------------------------------
// Scratch (static __device__ arrays; no allocation anywhere)
// ---------------------------------------------------------------------------
__device__ float g_bufA[100663296];             // 2T*1024 == T*2048  (g / h)
__device__ float g_bufB[100663296];             // 2T*1024 == T*2048  (u)
__device__ float g_y  [(size_t)NSLOT * HID];    // per-slot expert output
__device__ float g_ys [(size_t)T_TOK * HID];    // shared-expert output
__device__ int   g_topk_idx[NSLOT];
__device__ float g_topk_w [NSLOT];
__device__ float g_sig    [T_TOK];
__device__ int   g_counts [NEXP];
__device__ int   g_offsets[NEXP];
__device__ int   g_cursor [NEXP];
__device__ int   g_slot_token[NSLOT];           // slot -> token
__device__ int   g_slot_of   [NSLOT];           // (token,k) -> slot

// ---------------------------------------------------------------------------
// helpers: tf32 rounding + mma
// ---------------------------------------------------------------------------
__device__ __forceinline__ uint32_t f2tf32(float x) {
    uint32_t r;
    asm("cvt.rna.tf32.f32 %0, %1;" : "=r"(r) : "f"(x));
    return r;
}

__device__ __forceinline__ void mma_tf32(float* c, const uint32_t* a,
                                         uint32_t b0, uint32_t b1) {
    asm volatile(
        "mma.sync.aligned.m16n8k8.row.col.f32.tf32.tf32.f32 "
        "{%0,%1,%2,%3},{%4,%5,%6,%7},{%8,%9},{%0,%1,%2,%3};"
        : "+f"(c[0]), "+f"(c[1]), "+f"(c[2]), "+f"(c[3])
        : "r"(a[0]), "r"(a[1]), "r"(a[2]), "r"(a[3]), "r"(b0), "r"(b1));
}

// ---------------------------------------------------------------------------
// 0) zero counters
// ---------------------------------------------------------------------------
__global__ void init_kernel() {
    int i = threadIdx.x;
    if (i < NEXP) { g_counts[i] = 0; g_cursor[i] = 0; }
}

// ---------------------------------------------------------------------------
// 1) router: logits, softmax, top-2, sigmoid(x@sgate); count experts
// ---------------------------------------------------------------------------
__global__ void __launch_bounds__(256) router_kernel(
    const float* __restrict__ x, const float* __restrict__ gw,
    const float* __restrict__ sg, float* __restrict__ logits_out)
{
    __shared__ float s_gw[HID * NEXP];
    __shared__ float s_sg[HID];
    for (int i = threadIdx.x; i < HID * NEXP; i += 256) s_gw[i] = gw[i];
    for (int i = threadIdx.x; i < HID; i += 256) s_sg[i] = sg[i];
    __syncthreads();

    int warp = threadIdx.x >> 5, lane = threadIdx.x & 31;
    int t = blockIdx.x * 8 + warp;
    const float* xr = x + (size_t)t * HID;

    float acc[NEXP];
#pragma unroll
    for (int e = 0; e < NEXP; e++) acc[e] = 0.f;
    float accs = 0.f;

#pragma unroll 4
    for (int i = 0; i < 16; i++) {
        int h = i * 32 + lane;
        float xv = xr[h];
#pragma unroll
        for (int e = 0; e < NEXP; e++) acc[e] += xv * s_gw[h * NEXP + e];
        accs += xv * s_sg[h];
    }
#pragma unroll
    for (int off = 16; off; off >>= 1) {
#pragma unroll
        for (int e = 0; e < NEXP; e++)
            acc[e] += __shfl_xor_sync(0xffffffff, acc[e], off);
        accs += __shfl_xor_sync(0xffffffff, accs, off);
    }

    if (lane == 0) {
        if (logits_out) {
#pragma unroll
            for (int e = 0; e < NEXP; e++) logits_out[(size_t)t * NEXP + e] = acc[e];
        }
        float m = acc[0];
#pragma unroll
        for (int e = 1; e < NEXP; e++) m = fmaxf(m, acc[e]);
        float p[NEXP], sum = 0.f;
#pragma unroll
        for (int e = 0; e < NEXP; e++) { p[e] = expf(acc[e] - m); sum += p[e]; }
        float inv = 1.f / sum;
#pragma unroll
        for (int e = 0; e < NEXP; e++) p[e] *= inv;

        int i1 = 0;
#pragma unroll
        for (int e = 1; e < NEXP; e++) if (p[e] > p[i1]) i1 = e;
        int i2 = (i1 == 0) ? 1 : 0;
#pragma unroll
        for (int e = 0; e < NEXP; e++) if (e != i1 && e != i2 && p[e] > p[i2]) i2 = e;

        g_topk_idx[2 * t]     = i1; g_topk_w[2 * t]     = p[i1];
        g_topk_idx[2 * t + 1] = i2; g_topk_w[2 * t + 1] = p[i2];
        atomicAdd(&g_counts[i1], 1);
        atomicAdd(&g_counts[i2], 1);
        g_sig[t] = 1.f / (1.f + expf(-accs));
    }
}

// ---------------------------------------------------------------------------
// 2) exclusive prefix over 8 counts
// ---------------------------------------------------------------------------
__global__ void prefix_kernel() {
    if (threadIdx.x == 0) {
        int s = 0;
        for (int e = 0; e < NEXP; e++) { g_offsets[e] = s; g_cursor[e] = s; s += g_counts[e]; }
    }
}

// ---------------------------------------------------------------------------
// 3) scatter tokens into per-expert slot lists
// ---------------------------------------------------------------------------
__global__ void scatter_kernel() {
    int t = blockIdx.x * 256 + threadIdx.x;
    if (t >= T_TOK) return;
#pragma unroll
    for (int k = 0; k < 2; k++) {
        int e = g_topk_idx[2 * t + k];
        int pos = atomicAdd(&g_cursor[e], 1);
        g_slot_token[pos] = t;
        g_slot_of[2 * t + k] = pos;
    }
}

// ---------------------------------------------------------------------------
// 4) tf32 tensor-core GEMM, 128x128 block tile, K-tile 32, 256 threads.
//    8 warps, each 64x32 via 4x4 grid of mma.sync.m16n8k8.tf32.
//    Register prefetch of next K-tile overlaps the mma stage.
// ---------------------------------------------------------------------------
__global__ void __launch_bounds__(256, 1) sgemm_tc_kernel(
    const float* __restrict__ A, const float* __restrict__ B, float* __restrict__ C,
    int N, int K, long strideB, int Mfixed, int useCounts, int useGather)
{
    __shared__ float As[128][36];   // [m][k], padded to 144B rows
    __shared__ float Bs[32][136];   // [k][n], padded to 544B rows

    int e = blockIdx.z;
    int M, base;
    if (useCounts) { M = g_counts[e]; base = g_offsets[e]; }
    else           { M = Mfixed;      base = 0; }
    int row0 = blockIdx.y * 128;
    if (row0 >= M) return;
    int col0 = blockIdx.x * 128;
    const float* Bp = B + (size_t)e * strideB;

    int tid  = threadIdx.x;
    int lane = tid & 31;
    int wid  = tid >> 5;
    int wm   = (wid & 1) * 64;     // warp M offset within block tile
    int wn   = (wid >> 1) * 32;    // warp N offset

    // ---- global load lanes: 4 float4 of A + 4 float4 of B per thread ----
    // A: v = tid + j*256 -> row = v>>3 (0..127), colq = v&7 (k within tile /4)
    const float* aptr[4];
#pragma unroll
    for (int j = 0; j < 4; j++) {
        int v = tid + j * 256;
        int r = v >> 3;
        int gr = row0 + r; if (gr > M - 1) gr = M - 1;
        long arow = useGather ? (long)g_slot_token[base + gr] : (long)(base + gr);
        aptr[j] = A + (size_t)arow * K + (v & 7) * 4;
    }
    // B: v -> row = v>>5 (0..31), colq = v&31
    const float* bptr[4];
#pragma unroll
    for (int j = 0; j < 4; j++) {
        int v = tid + j * 256;
        bptr[j] = Bp + (size_t)(v >> 5) * N + col0 + (v & 31) * 4;
    }

    float acc[4][4][4];
#pragma unroll
    for (int mi = 0; mi < 4; mi++)
#pragma unroll
        for (int ni = 0; ni < 4; ni++)
#pragma unroll
            for (int q = 0; q < 4; q++) acc[mi][ni][q] = 0.f;

    int nk = K >> 5;                // K-tiles of 32

    // prologue: stage first tile into registers
    float4 sa[4], sb[4];
#pragma unroll
    for (int j = 0; j < 4; j++) { sa[j] = *(const float4*)aptr[j]; aptr[j] += 32; }
#pragma unroll
    for (int j = 0; j < 4; j++) { sb[j] = *(const float4*)bptr[j]; bptr[j] += (size_t)32 * N; }

    for (int kt = 0; kt < nk; kt++) {
        // commit staged tile to smem (with tf32 rounding)
#pragma unroll
        for (int j = 0; j < 4; j++) {
            int v = tid + j * 256;
            float* d = &As[v >> 3][(v & 7) * 4];
            d[0] = __uint_as_float(f2tf32(sa[j].x));
            d[1] = __uint_as_float(f2tf32(sa[j].y));
            d[2] = __uint_as_float(f2tf32(sa[j].z));
            d[3] = __uint_as_float(f2tf32(sa[j].w));
        }
#pragma unroll
        for (int j = 0; j < 4; j++) {
            int v = tid + j * 256;
            float* d = &Bs[v >> 5][(v & 31) * 4];
            d[0] = __uint_as_float(f2tf32(sb[j].x));
            d[1] = __uint_as_float(f2tf32(sb[j].y));
            d[2] = __uint_as_float(f2tf32(sb[j].z));
            d[3] = __uint_as_float(f2tf32(sb[j].w));
        }
        __syncthreads();

        // prefetch next tile while mma runs
        if (kt + 1 < nk) {
#pragma unroll
            for (int j = 0; j < 4; j++) { sa[j] = *(const float4*)aptr[j]; aptr[j] += 32; }
#pragma unroll
            for (int j = 0; j < 4; j++) { sb[j] = *(const float4*)bptr[j]; bptr[j] += (size_t)32 * N; }
        }

        // 4 k-steps of k=8
#pragma unroll
        for (int ks = 0; ks < 4; ks++) {
            int k0 = ks * 8;
            uint32_t af[4][4];
#pragma unroll
            for (int mi = 0; mi < 4; mi++) {
                int r = wm + mi * 16 + (lane >> 2);
                int kc = k0 + (lane & 3);
                af[mi][0] = __float_as_uint(As[r][kc]);
                af[mi][1] = __float_as_uint(As[r + 8][kc]);
                af[mi][2] = __float_as_uint(As[r][kc + 4]);
                af[mi][3] = __float_as_uint(As[r + 8][kc + 4]);
            }
#pragma unroll
            for (int ni = 0; ni < 4; ni++) {
                int c = wn + ni * 8 + (lane >> 2);
                uint32_t b0 = __float_as_uint(Bs[k0 + (lane & 3)][c]);
                uint32_t b1 = __float_as_uint(Bs[k0 + 4 + (lane & 3)][c]);
#pragma unroll
                for (int mi = 0; mi < 4; mi++)
                    mma_tf32(acc[mi][ni], af[mi], b0, b1);
            }
        }
        __syncthreads();
    }

    // epilogue: c0,c1 at (row, 2*(lane&3)+{0,1}), c2,c3 at row+8
#pragma unroll
    for (int mi = 0; mi < 4; mi++) {
        int r0 = row0 + wm + mi * 16 + (lane >> 2);
        int r1 = r0 + 8;
#pragma unroll
        for (int ni = 0; ni < 4; ni++) {
            int c = col0 + wn + ni * 8 + (lane & 3) * 2;
            if (r0 < M) {
                float* p = C + (size_t)(base + r0) * N + c;
                p[0] = acc[mi][ni][0]; p[1] = acc[mi][ni][1];
            }
            if (r1 < M) {
                float* p = C + (size_t)(base + r1) * N + c;
                p[0] = acc[mi][ni][2]; p[1] = acc[mi][ni][3];
            }
        }
    }
}

// ---------------------------------------------------------------------------
// 5) SwiGLU activation: a = silu(a) * b
// ---------------------------------------------------------------------------
__global__ void __launch_bounds__(256) act_kernel(float* __restrict__ a,
                                                  const float* __restrict__ b, int n4)
{
    int i = blockIdx.x * 256 + threadIdx.x;
    if (i >= n4) return;
    float4 g = ((const float4*)a)[i];
    float4 u = ((const float4*)b)[i];
    float4 r;
    r.x = g.x * (1.f / (1.f + __expf(-g.x))) * u.x;
    r.y = g.y * (1.f / (1.f + __expf(-g.y))) * u.y;
    r.z = g.z * (1.f / (1.f + __expf(-g.z))) * u.z;
    r.w = g.w * (1.f / (1.f + __expf(-g.w))) * u.w;
    ((float4*)a)[i] = r;
}

// ---------------------------------------------------------------------------
// 6) combine: out[t] = w0*y[s0] + w1*y[s1] + sig[t]*ys[t]
// ---------------------------------------------------------------------------
__global__ void __launch_bounds__(128) combine_kernel(float* __restrict__ out)
{
    int t = blockIdx.x;
    int j = threadIdx.x;
    float w0 = g_topk_w[2 * t], w1 = g_topk_w[2 * t + 1];
    int   s0 = g_slot_of[2 * t], s1 = g_slot_of[2 * t + 1];
    float sg = g_sig[t];
    const float4* y4  = (const float4*)g_y;
    const float4* ys4 = (const float4*)g_ys;
    float4 a = y4[(size_t)s0 * 128 + j];
    float4 b = y4[(size_t)s1 * 128 + j];
    float4 c = ys4[(size_t)t * 128 + j];
    float4 r;
    r.x = w0 * a.x + w1 * b.x + sg * c.x;
    r.y = w0 * a.y + w1 * b.y + sg * c.y;
    r.z = w0 * a.z + w1 * b.z + sg * c.z;
    r.w = w0 * a.w + w1 * b.w + sg * c.w;
    ((float4*)out)[(size_t)t * 128 + j] = r;
}

// ---------------------------------------------------------------------------
// launch
// ---------------------------------------------------------------------------
extern "C" void kernel_launch(void* const* d_in, const int* in_sizes, int n_in,
                              void* d_out, int out_size)
{
    const float* x     = (const float*)d_in[0];
    const float* gate  = (const float*)d_in[1];
    const float* w1    = (const float*)d_in[2];
    const float* w2    = (const float*)d_in[3];
    const float* w3    = (const float*)d_in[4];
    const float* sw1   = (const float*)d_in[5];
    const float* sw2   = (const float*)d_in[6];
    const float* sw3   = (const float*)d_in[7];
    const float* sgate = (const float*)d_in[8];
    float* out = (float*)d_out;

    float* logits = nullptr;
    if ((size_t)out_size >= (size_t)T_TOK * HID + (size_t)T_TOK * NEXP)
        logits = out + (size_t)T_TOK * HID;

    float* bufA = nullptr; float* bufB = nullptr; float* ybuf = nullptr; float* ysbuf = nullptr;
    cudaGetSymbolAddress((void**)&bufA,  g_bufA);
    cudaGetSymbolAddress((void**)&bufB,  g_bufB);
    cudaGetSymbolAddress((void**)&ybuf,  g_y);
    cudaGetSymbolAddress((void**)&ysbuf, g_ys);

    init_kernel<<<1, 32>>>();
    router_kernel<<<T_TOK / 8, 256>>>(x, gate, sgate, logits);
    prefix_kernel<<<1, 32>>>();
    scatter_kernel<<<T_TOK / 256, 256>>>();

    // MoE stage A: g = X_g @ w1[e], u = X_g @ w3[e]   (gathered rows)
    sgemm_tc_kernel<<<dim3(MOEI / 128, T_TOK / 128, NEXP), 256>>>(
        x, w1, bufA, MOEI, HID, (long)HID * MOEI, 0, 1, 1);
    sgemm_tc_kernel<<<dim3(MOEI / 128, T_TOK / 128, NEXP), 256>>>(
        x, w3, bufB, MOEI, HID, (long)HID * MOEI, 0, 1, 1);
    act_kernel<<<100663296 / (256 * 4), 256>>>(bufA, bufB, 100663296 / 4);
    // MoE stage B: y_slot = h @ w2[e]   (slot rows, no gather)
    sgemm_tc_kernel<<<dim3(HID / 128, T_TOK / 128, NEXP), 256>>>(
        bufA, w2, ybuf, HID, MOEI, (long)MOEI * HID, 0, 1, 0);

    // Shared expert (dense over all T tokens)
    sgemm_tc_kernel<<<dim3(SHI / 128, T_TOK / 128, 1), 256>>>(
        x, sw1, bufA, SHI, HID, 0L, T_TOK, 0, 0);
    sgemm_tc_kernel<<<dim3(SHI / 128, T_TOK / 128, 1), 256>>>(
        x, sw3, bufB, SHI, HID, 0L, T_TOK, 0, 0);
    act_kernel<<<100663296 / (256 * 4), 256>>>(bufA, bufB, 100663296 / 4);
    sgemm_tc_kernel<<<dim3(HID / 128, T_TOK / 128, 1), 256>>>(
        bufA, sw2, ysbuf, HID, SHI, 0L, T_TOK, 0, 0);

    combine_kernel<<<T_TOK, 128>>>(out);
}